// round 2
// baseline (speedup 1.0000x reference)
#include <cuda_runtime.h>
#include <cuda_bf16.h>
#include <math.h>

// Problem constants
#define NN     50000
#define FIN    256
#define NH     4
#define NR     4
#define FF     64
#define NE     500000
#define CPROJ  1024          // NH*NR*FF
#define CTOT   1280          // CPROJ + NH*FF (skip)

// ---------------- scratch (device globals; no allocation allowed) ----------------
__device__ float    g_ps[(size_t)NN * CTOT];          // [n][1280]: proj(0..1023) | skip(1024..1279)
__device__ float    g_agg[(size_t)NN * NR * NH * FF]; // [(n*4+r)*4+h)*64+f]
__device__ float    g_e[(size_t)NE * NH];             // per-edge scores -> exp
__device__ float    g_ssrc[(size_t)NN * NH * NR];     // [n*16 + h*4 + r]
__device__ float    g_strg[(size_t)NN * NH * NR];
__device__ float    g_denom[(size_t)NN * NR * NH];    // [(n*4+r)*4+h]
__device__ float    g_wcat[(size_t)CTOT * FIN];       // concatenated weights
__device__ unsigned g_m_u[NR * NH];                   // ordered-uint encoded per-(rel,head) max

// ---------------- helpers ----------------
__device__ __forceinline__ unsigned fenc(float f) {
    unsigned u = __float_as_uint(f);
    return (u & 0x80000000u) ? ~u : (u | 0x80000000u);
}
__device__ __forceinline__ float fdec(unsigned u) {
    return (u & 0x80000000u) ? __uint_as_float(u & 0x7fffffffu) : __uint_as_float(~u);
}

// ---------------- K0: concat [W_proj; W_skip] -> g_wcat ----------------
__global__ void wcat_kernel(const float* __restrict__ Wp, const float* __restrict__ Ws) {
    int idx = blockIdx.x * blockDim.x + threadIdx.x;
    int tot = CTOT * FIN;
    for (; idx < tot; idx += gridDim.x * blockDim.x) {
        g_wcat[idx] = (idx < CPROJ * FIN) ? Wp[idx] : Ws[idx - CPROJ * FIN];
    }
}

// ---------------- K1: zero scratch ----------------
__global__ void zero_kernel() {
    size_t idx = (size_t)blockIdx.x * blockDim.x + threadIdx.x;
    size_t naggv = (size_t)NN * NR * NH * FF / 4;
    float4 z = make_float4(0.f, 0.f, 0.f, 0.f);
    float4* agg4 = reinterpret_cast<float4*>(g_agg);
    for (size_t i = idx; i < naggv; i += (size_t)gridDim.x * blockDim.x) agg4[i] = z;
    size_t ndv = (size_t)NN * NR * NH / 4;
    float4* den4 = reinterpret_cast<float4*>(g_denom);
    for (size_t i = idx; i < ndv; i += (size_t)gridDim.x * blockDim.x) den4[i] = z;
    if (idx < NR * NH) g_m_u[idx] = 0u;
}

// ---------------- K2: SGEMM  C[N,1280] = x[N,256] @ Wcat^T ----------------
// Tiles: BM=128, BN=64, BK=16; 256 threads; each thread 8x4 outputs.
__global__ void __launch_bounds__(256) gemm_kernel(const float* __restrict__ A) {
    __shared__ float As[16][128];
    __shared__ float Bs[16][64];
    int t = threadIdx.x;
    int row0 = blockIdx.y * 128;
    int col0 = blockIdx.x * 64;
    int tx = t & 15, ty = t >> 4;

    float acc[8][4];
#pragma unroll
    for (int i = 0; i < 8; i++)
#pragma unroll
        for (int j = 0; j < 4; j++) acc[i][j] = 0.f;

    for (int k0 = 0; k0 < FIN; k0 += 16) {
        // load A tile (128x16) transposed into As[k][m]
#pragma unroll
        for (int i = 0; i < 2; i++) {
            int v = t + i * 256;          // 0..511 vectors
            int r = v >> 2;               // 0..127
            int c4 = v & 3;               // k-chunk
            int grow = row0 + r;
            float4 f4 = make_float4(0.f, 0.f, 0.f, 0.f);
            if (grow < NN) f4 = *reinterpret_cast<const float4*>(A + (size_t)grow * FIN + k0 + c4 * 4);
            As[c4 * 4 + 0][r] = f4.x;
            As[c4 * 4 + 1][r] = f4.y;
            As[c4 * 4 + 2][r] = f4.z;
            As[c4 * 4 + 3][r] = f4.w;
        }
        // load B tile (64x16) transposed into Bs[k][o]
        {
            int cc = t >> 2;
            int c4 = t & 3;
            float4 f4 = *reinterpret_cast<const float4*>(g_wcat + (size_t)(col0 + cc) * FIN + k0 + c4 * 4);
            Bs[c4 * 4 + 0][cc] = f4.x;
            Bs[c4 * 4 + 1][cc] = f4.y;
            Bs[c4 * 4 + 2][cc] = f4.z;
            Bs[c4 * 4 + 3][cc] = f4.w;
        }
        __syncthreads();
#pragma unroll
        for (int k = 0; k < 16; k++) {
            float a[8], b[4];
            *reinterpret_cast<float4*>(&a[0]) = *reinterpret_cast<float4*>(&As[k][ty * 8]);
            *reinterpret_cast<float4*>(&a[4]) = *reinterpret_cast<float4*>(&As[k][ty * 8 + 4]);
            *reinterpret_cast<float4*>(&b[0]) = *reinterpret_cast<float4*>(&Bs[k][tx * 4]);
#pragma unroll
            for (int i = 0; i < 8; i++)
#pragma unroll
                for (int j = 0; j < 4; j++) acc[i][j] = fmaf(a[i], b[j], acc[i][j]);
        }
        __syncthreads();
    }
#pragma unroll
    for (int i = 0; i < 8; i++) {
        int grow = row0 + ty * 8 + i;
        if (grow < NN) {
            float4 o = make_float4(acc[i][0], acc[i][1], acc[i][2], acc[i][3]);
            *reinterpret_cast<float4*>(&g_ps[(size_t)grow * CTOT + col0 + tx * 4]) = o;
        }
    }
}

// ---------------- K3: attention scores per (n,h,r) ----------------
__global__ void __launch_bounds__(256) scores_kernel(const float* __restrict__ score_src,
                                                     const float* __restrict__ score_trg) {
    int n = blockIdx.x;
    int t = threadIdx.x;
    int w = t >> 5, lane = t & 31;
    const float* pr_base = g_ps + (size_t)n * CTOT;
#pragma unroll
    for (int pi = 0; pi < 2; pi++) {
        int p = w * 2 + pi;   // p = h*4 + r
        const float* pr = pr_base + p * 64;
        float v1 = pr[lane] * score_src[p * 64 + lane] + pr[lane + 32] * score_src[p * 64 + lane + 32];
        float v2 = pr[lane] * score_trg[p * 64 + lane] + pr[lane + 32] * score_trg[p * 64 + lane + 32];
#pragma unroll
        for (int off = 16; off > 0; off >>= 1) {
            v1 += __shfl_down_sync(0xffffffffu, v1, off);
            v2 += __shfl_down_sync(0xffffffffu, v2, off);
        }
        if (lane == 0) {
            g_ssrc[n * 16 + p] = v1;
            g_strg[n * 16 + p] = v2;
        }
    }
}

// ---------------- K4: edge pass 1 — leaky relu + per-(rel,head) max ----------------
__global__ void __launch_bounds__(256) edge1_kernel(const int* __restrict__ src,
                                                    const int* __restrict__ trg,
                                                    const int* __restrict__ rel) {
    __shared__ unsigned sm[16];
    int t = threadIdx.x;
    if (t < 16) sm[t] = 0u;
    __syncthreads();
    int e = blockIdx.x * 256 + t;
    if (e < NE) {
        int r = rel[e];
        int is = src[e] * 16;
        int it = trg[e] * 16;
#pragma unroll
        for (int h = 0; h < NH; h++) {
            float v = g_ssrc[is + h * 4 + r] + g_strg[it + h * 4 + r];
            v = (v > 0.f) ? v : 0.2f * v;
            g_e[(size_t)e * NH + h] = v;
            atomicMax(&sm[r * 4 + h], fenc(v));
        }
    }
    __syncthreads();
    if (t < 16 && sm[t] != 0u) atomicMax(&g_m_u[t], sm[t]);
}

// ---------------- K5: edge pass 2 — exp + segment-sum denominator ----------------
__global__ void __launch_bounds__(256) edge2_kernel(const int* __restrict__ trg,
                                                    const int* __restrict__ rel) {
    int e = blockIdx.x * 256 + threadIdx.x;
    if (e >= NE) return;
    int r = rel[e];
    int tg = trg[e];
#pragma unroll
    for (int h = 0; h < NH; h++) {
        float m = fdec(g_m_u[r * 4 + h]);
        float ex = expf(g_e[(size_t)e * NH + h] - m);
        g_e[(size_t)e * NH + h] = ex;
        atomicAdd(&g_denom[(tg * 4 + r) * 4 + h], ex);
    }
}

// ---------------- K6: edge pass 3 — weighted gather + scatter into agg ----------------
// one warp per edge
__global__ void __launch_bounds__(256) edge3_kernel(const int* __restrict__ src,
                                                    const int* __restrict__ trg,
                                                    const int* __restrict__ rel) {
    int gw = (blockIdx.x * blockDim.x + threadIdx.x) >> 5;
    int lane = threadIdx.x & 31;
    if (gw >= NE) return;
    int e = gw;
    int r = rel[e];
    int s = src[e];
    int tg = trg[e];
#pragma unroll
    for (int h = 0; h < NH; h++) {
        float ex  = g_e[(size_t)e * NH + h];
        float den = g_denom[(tg * 4 + r) * 4 + h];
        float att = ex / (den + 1e-16f);
        const float* pp = g_ps + (size_t)s * CTOT + h * 256 + r * 64;
        float* ag = g_agg + ((size_t)(tg * 4 + r) * 4 + h) * 64;
        atomicAdd(&ag[lane],      pp[lane]      * att);
        atomicAdd(&ag[lane + 32], pp[lane + 32] * att);
    }
}

// ---------------- K7: node kernel — MLP score + rel softmax + skip + ELU + LN ----------------
__global__ void __launch_bounds__(256) node_kernel(const float* __restrict__ W1, const float* __restrict__ b1,
                                                   const float* __restrict__ W2, const float* __restrict__ b2,
                                                   const float* __restrict__ W3, const float* __restrict__ b3,
                                                   const float* __restrict__ bias, const float* __restrict__ gamma,
                                                   const float* __restrict__ beta, float* __restrict__ out) {
    __shared__ float W1s[64 * 65];
    __shared__ float W2s[64 * 65];
    __shared__ float a_s[1024];
    __shared__ float h1s[1024];
    __shared__ float h2s[1024];
    __shared__ float scs[16];
    __shared__ float alphas[16];
    __shared__ float red[18];

    int n = blockIdx.x;
    int t = threadIdx.x;

    for (int idx = t; idx < 4096; idx += 256) {
        int i = idx >> 6, j = idx & 63;
        W1s[i * 65 + j] = W1[idx];
        W2s[i * 65 + j] = W2[idx];
    }
    for (int idx = t; idx < 1024; idx += 256) {
        int p = idx >> 6, f = idx & 63;
        int h = p >> 2, r = p & 3;
        a_s[idx] = g_agg[((size_t)(n * 4 + r) * 4 + h) * 64 + f];
    }
    __syncthreads();

    // layer 1: h1 = relu(a @ W1^T + b1) per (h,r)
    for (int idx = t; idx < 1024; idx += 256) {
        int p = idx >> 6, i = idx & 63;
        float sacc = b1[i];
        const float* ap = &a_s[p * 64];
        const float* wp = &W1s[i * 65];
#pragma unroll
        for (int j = 0; j < 64; j++) sacc = fmaf(ap[j], wp[j], sacc);
        h1s[idx] = fmaxf(sacc, 0.f);
    }
    __syncthreads();

    // layer 2
    for (int idx = t; idx < 1024; idx += 256) {
        int p = idx >> 6, i = idx & 63;
        float sacc = b2[i];
        const float* ap = &h1s[p * 64];
        const float* wp = &W2s[i * 65];
#pragma unroll
        for (int j = 0; j < 64; j++) sacc = fmaf(ap[j], wp[j], sacc);
        h2s[idx] = fmaxf(sacc, 0.f);
    }
    __syncthreads();

    // score head + mish
    if (t < 16) {
        float sacc = b3[0];
        const float* ap = &h2s[t * 64];
#pragma unroll
        for (int j = 0; j < 64; j++) sacc = fmaf(ap[j], W3[j], sacc);
        float sp = (sacc > 20.f) ? sacc : log1pf(expf(sacc));
        scs[t] = sacc * tanhf(sp);
    }
    __syncthreads();

    // softmax over relations per head
    if (t < 4) {
        float mx = -1e30f;
#pragma unroll
        for (int r = 0; r < 4; r++) mx = fmaxf(mx, scs[t * 4 + r]);
        float ev[4], ssum = 0.f;
#pragma unroll
        for (int r = 0; r < 4; r++) { ev[r] = expf(scs[t * 4 + r] - mx); ssum += ev[r]; }
#pragma unroll
        for (int r = 0; r < 4; r++) alphas[t * 4 + r] = ev[r] / ssum;
    }
    __syncthreads();

    // weighted sum over relations + skip + bias + ELU
    int hh = t >> 6, f = t & 63;
    float o = 0.f;
#pragma unroll
    for (int r = 0; r < 4; r++) o = fmaf(a_s[(hh * 4 + r) * 64 + f], alphas[hh * 4 + r], o);
    o += g_ps[(size_t)n * CTOT + CPROJ + t];
    o += bias[t];
    o = (o > 0.f) ? o : expm1f(o);

    // layernorm over 256
    float s1 = o, s2 = o * o;
#pragma unroll
    for (int off = 16; off > 0; off >>= 1) {
        s1 += __shfl_down_sync(0xffffffffu, s1, off);
        s2 += __shfl_down_sync(0xffffffffu, s2, off);
    }
    int wid = t >> 5, lane = t & 31;
    if (lane == 0) { red[wid] = s1; red[8 + wid] = s2; }
    __syncthreads();
    if (t == 0) {
        float S1 = 0.f, S2 = 0.f;
#pragma unroll
        for (int w = 0; w < 8; w++) { S1 += red[w]; S2 += red[8 + w]; }
        float mu = S1 * (1.f / 256.f);
        float var = S2 * (1.f / 256.f) - mu * mu;
        red[16] = mu;
        red[17] = rsqrtf(var + 1e-5f);
    }
    __syncthreads();
    float mu = red[16], rstd = red[17];
    out[(size_t)n * 256 + t] = (o - mu) * rstd * gamma[t] + beta[t];
}

// ---------------- launch ----------------
extern "C" void kernel_launch(void* const* d_in, const int* in_sizes, int n_in,
                              void* d_out, int out_size) {
    const float* x         = (const float*)d_in[0];
    const int*   src       = (const int*)d_in[1];
    const int*   trg       = (const int*)d_in[2];
    const int*   rel       = (const int*)d_in[3];
    // d_in[4] = node_to_graph_map (unused)
    const float* W_proj    = (const float*)d_in[5];
    const float* score_src = (const float*)d_in[6];
    const float* score_trg = (const float*)d_in[7];
    const float* W1        = (const float*)d_in[8];
    const float* b1        = (const float*)d_in[9];
    const float* W2        = (const float*)d_in[10];
    const float* b2        = (const float*)d_in[11];
    const float* W3        = (const float*)d_in[12];
    const float* b3        = (const float*)d_in[13];
    const float* W_skip    = (const float*)d_in[14];
    const float* bias      = (const float*)d_in[15];
    const float* gamma     = (const float*)d_in[16];
    const float* beta      = (const float*)d_in[17];
    float* out = (float*)d_out;

    wcat_kernel<<<320, 512>>>(W_proj, W_skip);
    zero_kernel<<<8192, 256>>>();

    dim3 ggrid(CTOT / 64, (NN + 127) / 128);
    gemm_kernel<<<ggrid, 256>>>(x);

    scores_kernel<<<NN, 256>>>(score_src, score_trg);

    int eb = (NE + 255) / 256;
    edge1_kernel<<<eb, 256>>>(src, trg, rel);
    edge2_kernel<<<eb, 256>>>(trg, rel);
    edge3_kernel<<<(NE * 32 + 255) / 256, 256>>>(src, trg, rel);

    node_kernel<<<NN, 256>>>(W1, b1, W2, b2, W3, b3, bias, gamma, beta, out);
}

// round 4
// speedup vs baseline: 1.4730x; 1.4730x over previous
#include <cuda_runtime.h>
#include <cuda_bf16.h>
#include <math.h>

// Problem constants
#define NN     50000
#define FIN    256
#define NH     4
#define NR     4
#define FF     64
#define NE     500000
#define CPROJ  1024          // NH*NR*FF
#define CTOT   1280          // CPROJ + NH*FF (skip)
#define KEXT   768           // 3 * FIN (split-bf16 compensated K)

// ---------------- scratch (device globals; no allocation allowed) ----------------
__device__ float         g_ps[(size_t)NN * CTOT];          // [n][1280]: proj | skip (fp32)
__device__ float         g_agg[(size_t)NN * NR * NH * FF]; // [((n*4+r)*4+h)*64+f]
__device__ float         g_e[(size_t)NE * NH];
__device__ float         g_ssrc[(size_t)NN * NH * NR];
__device__ float         g_strg[(size_t)NN * NH * NR];
__device__ float         g_denom[(size_t)NN * NR * NH];
__device__ unsigned      g_m_u[NR * NH];
__device__ __nv_bfloat16 g_aext[(size_t)NN * KEXT];        // [n][768] = [x_hi | x_lo | x_hi]
__device__ __nv_bfloat16 g_bext[(size_t)CTOT * KEXT];      // [c][768] = [W_hi | W_hi | W_lo]

// ---------------- helpers ----------------
__device__ __forceinline__ unsigned fenc(float f) {
    unsigned u = __float_as_uint(f);
    return (u & 0x80000000u) ? ~u : (u | 0x80000000u);
}
__device__ __forceinline__ float fdec(unsigned u) {
    return (u & 0x80000000u) ? __uint_as_float(u & 0x7fffffffu) : __uint_as_float(~u);
}
__device__ __forceinline__ void bsplit(float w, __nv_bfloat16& hi, __nv_bfloat16& lo) {
    hi = __float2bfloat16(w);
    lo = __float2bfloat16(w - __bfloat162float(hi));
}
__device__ __forceinline__ void mma_bf16(float* c, unsigned a0, unsigned a1, unsigned a2,
                                         unsigned a3, unsigned b0, unsigned b1) {
    asm volatile(
        "mma.sync.aligned.m16n8k16.row.col.f32.bf16.bf16.f32 "
        "{%0,%1,%2,%3}, {%4,%5,%6,%7}, {%8,%9}, {%0,%1,%2,%3};\n"
        : "+f"(c[0]), "+f"(c[1]), "+f"(c[2]), "+f"(c[3])
        : "r"(a0), "r"(a1), "r"(a2), "r"(a3), "r"(b0), "r"(b1));
}

// ---------------- prep kernels ----------------
__global__ void prep_wext_kernel(const float* __restrict__ Wp, const float* __restrict__ Ws) {
    int idx = blockIdx.x * blockDim.x + threadIdx.x;
    if (idx >= CTOT * FIN) return;
    int c = idx >> 8, k = idx & 255;
    float w = (c < CPROJ) ? Wp[idx] : Ws[(c - CPROJ) * FIN + k];
    __nv_bfloat16 hi, lo; bsplit(w, hi, lo);
    size_t b = (size_t)c * KEXT;
    g_bext[b + k] = hi; g_bext[b + 256 + k] = hi; g_bext[b + 512 + k] = lo;
}

__global__ void prep_aext_kernel(const float* __restrict__ x) {
    int idx = blockIdx.x * blockDim.x + threadIdx.x;
    int tot = NN * FIN;
    for (; idx < tot; idx += gridDim.x * blockDim.x) {
        int n = idx >> 8, k = idx & 255;
        float w = x[idx];
        __nv_bfloat16 hi, lo; bsplit(w, hi, lo);
        size_t b = (size_t)n * KEXT;
        g_aext[b + k] = hi; g_aext[b + 256 + k] = lo; g_aext[b + 512 + k] = hi;
    }
}

// ---------------- K1: zero scratch ----------------
__global__ void zero_kernel() {
    size_t idx = (size_t)blockIdx.x * blockDim.x + threadIdx.x;
    size_t naggv = (size_t)NN * NR * NH * FF / 4;
    float4 z = make_float4(0.f, 0.f, 0.f, 0.f);
    float4* agg4 = reinterpret_cast<float4*>(g_agg);
    for (size_t i = idx; i < naggv; i += (size_t)gridDim.x * blockDim.x) agg4[i] = z;
    size_t ndv = (size_t)NN * NR * NH / 4;
    float4* den4 = reinterpret_cast<float4*>(g_denom);
    for (size_t i = idx; i < ndv; i += (size_t)gridDim.x * blockDim.x) den4[i] = z;
    if (idx < NR * NH) g_m_u[idx] = 0u;
}

// ---------------- K2: bf16 tensor-core GEMM  C[N,1280] = Aext[N,768] @ Bext^T ----------------
// BM=128, BN=128, BK=32; 256 thr = 8 warps (2x4); warp tile 64x32; mma m16n8k16
#define GS 40   // smem row stride in halves (32 + 8 pad -> conflict-free frag loads)
__global__ void __launch_bounds__(256) gemm_bf16_kernel() {
    __shared__ __nv_bfloat16 As[128 * GS];
    __shared__ __nv_bfloat16 Bs[128 * GS];
    int t = threadIdx.x;
    int lane = t & 31, w = t >> 5;
    int wm = w >> 2, wn = w & 3;       // wm 0..1 (64 rows), wn 0..3 (32 cols)
    int g = lane >> 2, tg = lane & 3;
    int row0 = blockIdx.y * 128;
    int col0 = blockIdx.x * 128;

    float acc[4][4][4];
#pragma unroll
    for (int i = 0; i < 4; i++)
#pragma unroll
        for (int j = 0; j < 4; j++)
#pragma unroll
            for (int q = 0; q < 4; q++) acc[i][j][q] = 0.f;

    int ar0 = t >> 2,          ac0 = (t & 3) * 8;
    int ar1 = (t + 256) >> 2,  ac1 = ((t + 256) & 3) * 8;

    for (int k0 = 0; k0 < KEXT; k0 += 32) {
        float4 av0 = make_float4(0.f, 0.f, 0.f, 0.f), av1 = av0;
        if (row0 + ar0 < NN) av0 = *reinterpret_cast<const float4*>(g_aext + (size_t)(row0 + ar0) * KEXT + k0 + ac0);
        if (row0 + ar1 < NN) av1 = *reinterpret_cast<const float4*>(g_aext + (size_t)(row0 + ar1) * KEXT + k0 + ac1);
        float4 bv0 = *reinterpret_cast<const float4*>(g_bext + (size_t)(col0 + ar0) * KEXT + k0 + ac0);
        float4 bv1 = *reinterpret_cast<const float4*>(g_bext + (size_t)(col0 + ar1) * KEXT + k0 + ac1);
        __syncthreads();
        *reinterpret_cast<float4*>(As + ar0 * GS + ac0) = av0;
        *reinterpret_cast<float4*>(As + ar1 * GS + ac1) = av1;
        *reinterpret_cast<float4*>(Bs + ar0 * GS + ac0) = bv0;
        *reinterpret_cast<float4*>(Bs + ar1 * GS + ac1) = bv1;
        __syncthreads();

#pragma unroll
        for (int kk = 0; kk < 32; kk += 16) {
            unsigned af[4][4], bf_[4][2];
#pragma unroll
            for (int mt = 0; mt < 4; mt++) {
                const __nv_bfloat16* ap = As + (wm * 64 + mt * 16 + g) * GS + kk + tg * 2;
                af[mt][0] = *reinterpret_cast<const unsigned*>(ap);
                af[mt][1] = *reinterpret_cast<const unsigned*>(ap + 8 * GS);
                af[mt][2] = *reinterpret_cast<const unsigned*>(ap + 8);
                af[mt][3] = *reinterpret_cast<const unsigned*>(ap + 8 * GS + 8);
            }
#pragma unroll
            for (int nt = 0; nt < 4; nt++) {
                const __nv_bfloat16* bp = Bs + (wn * 32 + nt * 8 + g) * GS + kk + tg * 2;
                bf_[nt][0] = *reinterpret_cast<const unsigned*>(bp);
                bf_[nt][1] = *reinterpret_cast<const unsigned*>(bp + 8);
            }
#pragma unroll
            for (int mt = 0; mt < 4; mt++)
#pragma unroll
                for (int nt = 0; nt < 4; nt++)
                    mma_bf16(acc[mt][nt], af[mt][0], af[mt][1], af[mt][2], af[mt][3],
                             bf_[nt][0], bf_[nt][1]);
        }
    }

#pragma unroll
    for (int mt = 0; mt < 4; mt++)
#pragma unroll
        for (int nt = 0; nt < 4; nt++) {
            int row = row0 + wm * 64 + mt * 16 + g;
            int col = col0 + wn * 32 + nt * 8 + tg * 2;
            if (row < NN) {
                float2 o = make_float2(acc[mt][nt][0], acc[mt][nt][1]);
                *reinterpret_cast<float2*>(g_ps + (size_t)row * CTOT + col) = o;
            }
            if (row + 8 < NN) {
                float2 o = make_float2(acc[mt][nt][2], acc[mt][nt][3]);
                *reinterpret_cast<float2*>(g_ps + (size_t)(row + 8) * CTOT + col) = o;
            }
        }
}

// ---------------- K3: attention scores per (n,h,r) ----------------
__global__ void __launch_bounds__(256) scores_kernel(const float* __restrict__ score_src,
                                                     const float* __restrict__ score_trg) {
    int n = blockIdx.x;
    int t = threadIdx.x;
    int w = t >> 5, lane = t & 31;
    const float* pr_base = g_ps + (size_t)n * CTOT;
#pragma unroll
    for (int pi = 0; pi < 2; pi++) {
        int p = w * 2 + pi;   // p = h*4 + r
        const float* pr = pr_base + p * 64;
        float v1 = pr[lane] * score_src[p * 64 + lane] + pr[lane + 32] * score_src[p * 64 + lane + 32];
        float v2 = pr[lane] * score_trg[p * 64 + lane] + pr[lane + 32] * score_trg[p * 64 + lane + 32];
#pragma unroll
        for (int off = 16; off > 0; off >>= 1) {
            v1 += __shfl_down_sync(0xffffffffu, v1, off);
            v2 += __shfl_down_sync(0xffffffffu, v2, off);
        }
        if (lane == 0) {
            g_ssrc[n * 16 + p] = v1;
            g_strg[n * 16 + p] = v2;
        }
    }
}

// ---------------- K4: edge pass 1 ----------------
__global__ void __launch_bounds__(256) edge1_kernel(const int* __restrict__ src,
                                                    const int* __restrict__ trg,
                                                    const int* __restrict__ rel) {
    __shared__ unsigned sm[16];
    int t = threadIdx.x;
    if (t < 16) sm[t] = 0u;
    __syncthreads();
    int e = blockIdx.x * 256 + t;
    if (e < NE) {
        int r = rel[e];
        int is = src[e] * 16;
        int it = trg[e] * 16;
#pragma unroll
        for (int h = 0; h < NH; h++) {
            float v = g_ssrc[is + h * 4 + r] + g_strg[it + h * 4 + r];
            v = (v > 0.f) ? v : 0.2f * v;
            g_e[(size_t)e * NH + h] = v;
            atomicMax(&sm[r * 4 + h], fenc(v));
        }
    }
    __syncthreads();
    if (t < 16 && sm[t] != 0u) atomicMax(&g_m_u[t], sm[t]);
}

// ---------------- K5: edge pass 2 ----------------
__global__ void __launch_bounds__(256) edge2_kernel(const int* __restrict__ trg,
                                                    const int* __restrict__ rel) {
    int e = blockIdx.x * 256 + threadIdx.x;
    if (e >= NE) return;
    int r = rel[e];
    int tg = trg[e];
#pragma unroll
    for (int h = 0; h < NH; h++) {
        float m = fdec(g_m_u[r * 4 + h]);
        float ex = expf(g_e[(size_t)e * NH + h] - m);
        g_e[(size_t)e * NH + h] = ex;
        atomicAdd(&g_denom[(tg * 4 + r) * 4 + h], ex);
    }
}

// ---------------- K6: edge pass 3 ----------------
__global__ void __launch_bounds__(256) edge3_kernel(const int* __restrict__ src,
                                                    const int* __restrict__ trg,
                                                    const int* __restrict__ rel) {
    int gw = (blockIdx.x * blockDim.x + threadIdx.x) >> 5;
    int lane = threadIdx.x & 31;
    if (gw >= NE) return;
    int e = gw;
    int r = rel[e];
    int s = src[e];
    int tg = trg[e];
#pragma unroll
    for (int h = 0; h < NH; h++) {
        float ex  = g_e[(size_t)e * NH + h];
        float den = g_denom[(tg * 4 + r) * 4 + h];
        float att = ex / (den + 1e-16f);
        const float* pp = g_ps + (size_t)s * CTOT + h * 256 + r * 64;
        float* ag = g_agg + ((size_t)(tg * 4 + r) * 4 + h) * 64;
        atomicAdd(&ag[lane],      pp[lane]      * att);
        atomicAdd(&ag[lane + 32], pp[lane + 32] * att);
    }
}

// ---------------- K7: fused node kernel with tensor-core MLP ----------------
// 8 nodes/block. M=128 rows (node-local (h,r) pairs), N=64, K=192 (split-bf16).
#define NS 200   // smem row stride in halves for 192-wide split tiles
#define NODE2_SMEM (128*NS*2*2 + 64*NS*2*2 + (64+64+64+128+128+32)*4)

__device__ __forceinline__ void mlp_layer(const __nv_bfloat16* __restrict__ Ain,
                                          const __nv_bfloat16* __restrict__ Wm,
                                          const float* __restrict__ bs,
                                          __nv_bfloat16* __restrict__ Hout, int t) {
    int lane = t & 31, w = t >> 5;
    int wm = w >> 2, wn = w & 3;        // wm 0..1 (64 rows), wn 0..3 (16 cols)
    int g = lane >> 2, tg = lane & 3;
    float acc[4][2][4];
#pragma unroll
    for (int i = 0; i < 4; i++)
#pragma unroll
        for (int j = 0; j < 2; j++)
#pragma unroll
            for (int q = 0; q < 4; q++) acc[i][j][q] = 0.f;

#pragma unroll
    for (int ks = 0; ks < 12; ks++) {
        int kk = ks * 16;
        unsigned af[4][4], bf_[2][2];
#pragma unroll
        for (int mt = 0; mt < 4; mt++) {
            const __nv_bfloat16* ap = Ain + (wm * 64 + mt * 16 + g) * NS + kk + tg * 2;
            af[mt][0] = *reinterpret_cast<const unsigned*>(ap);
            af[mt][1] = *reinterpret_cast<const unsigned*>(ap + 8 * NS);
            af[mt][2] = *reinterpret_cast<const unsigned*>(ap + 8);
            af[mt][3] = *reinterpret_cast<const unsigned*>(ap + 8 * NS + 8);
        }
#pragma unroll
        for (int nt = 0; nt < 2; nt++) {
            const __nv_bfloat16* bp = Wm + (wn * 16 + nt * 8 + g) * NS + kk + tg * 2;
            bf_[nt][0] = *reinterpret_cast<const unsigned*>(bp);
            bf_[nt][1] = *reinterpret_cast<const unsigned*>(bp + 8);
        }
#pragma unroll
        for (int mt = 0; mt < 4; mt++)
#pragma unroll
            for (int nt = 0; nt < 2; nt++)
                mma_bf16(acc[mt][nt], af[mt][0], af[mt][1], af[mt][2], af[mt][3],
                         bf_[nt][0], bf_[nt][1]);
    }
    __syncthreads();   // all reads of Ain/Hout done before (possibly in-place) writes
#pragma unroll
    for (int mt = 0; mt < 4; mt++)
#pragma unroll
        for (int nt = 0; nt < 2; nt++) {
            int row = wm * 64 + mt * 16 + g;
            int col = wn * 16 + nt * 8 + tg * 2;
#pragma unroll
            for (int q = 0; q < 4; q++) {
                int rr = row + ((q >> 1) ? 8 : 0);
                int cc = col + (q & 1);
                float h = fmaxf(acc[mt][nt][q] + bs[cc], 0.f);
                __nv_bfloat16 hi, lo; bsplit(h, hi, lo);
                Hout[rr * NS + cc] = hi;
                Hout[rr * NS + 64 + cc] = lo;
                Hout[rr * NS + 128 + cc] = hi;
            }
        }
    __syncthreads();
}

__global__ void __launch_bounds__(256) node2_kernel(
        const float* __restrict__ W1, const float* __restrict__ b1,
        const float* __restrict__ W2, const float* __restrict__ b2,
        const float* __restrict__ W3, const float* __restrict__ b3,
        const float* __restrict__ bias, const float* __restrict__ gamma,
        const float* __restrict__ beta, float* __restrict__ out) {
    extern __shared__ char nsm[];
    __nv_bfloat16* Asp = reinterpret_cast<__nv_bfloat16*>(nsm);   // 128*NS
    __nv_bfloat16* Hsp = Asp + 128 * NS;                          // 128*NS
    __nv_bfloat16* W1s = Hsp + 128 * NS;                          // 64*NS
    __nv_bfloat16* W2s = W1s + 64 * NS;                           // 64*NS
    float* W3s  = reinterpret_cast<float*>(W2s + 64 * NS);        // 64
    float* b1s  = W3s + 64;                                       // 64
    float* b2s  = b1s + 64;                                       // 64
    float* scs  = b2s + 64;                                       // 128
    float* alps = scs + 128;                                      // 128
    float* red  = alps + 128;                                     // 32

    int t = threadIdx.x;
    int node0 = blockIdx.x * 8;

    // load split weights
    for (int idx = t; idx < 4096; idx += 256) {
        int n_ = idx >> 6, k_ = idx & 63;
        __nv_bfloat16 hi, lo;
        bsplit(W1[idx], hi, lo);
        W1s[n_ * NS + k_] = hi; W1s[n_ * NS + 64 + k_] = hi; W1s[n_ * NS + 128 + k_] = lo;
        bsplit(W2[idx], hi, lo);
        W2s[n_ * NS + k_] = hi; W2s[n_ * NS + 64 + k_] = hi; W2s[n_ * NS + 128 + k_] = lo;
    }
    if (t < 64) { W3s[t] = W3[t]; b1s[t] = b1[t]; b2s[t] = b2[t]; }

    // load agg, split into Asp; row = ln*16 + h*4 + r
    for (int idx = t; idx < 8192; idx += 256) {
        int row = idx >> 6, f = idx & 63;
        int ln = row >> 4, p = row & 15, h = p >> 2, r = p & 3;
        int n = node0 + ln;
        float a = g_agg[(((size_t)n * 4 + r) * 4 + h) * 64 + f];
        __nv_bfloat16 hi, lo; bsplit(a, hi, lo);
        Asp[row * NS + f] = hi; Asp[row * NS + 64 + f] = lo; Asp[row * NS + 128 + f] = hi;
    }
    __syncthreads();

    mlp_layer(Asp, W1s, b1s, Hsp, t);   // h1
    mlp_layer(Hsp, W2s, b2s, Hsp, t);   // h2 (in-place)

    // score head + mish (per row)
    if (t < 128) {
        float sacc = b3[0];
        const __nv_bfloat16* hp = Hsp + t * NS;
#pragma unroll
        for (int j = 0; j < 64; j++) {
            float hv = __bfloat162float(hp[j]) + __bfloat162float(hp[64 + j]);
            sacc = fmaf(hv, W3s[j], sacc);
        }
        float sp = (sacc > 20.f) ? sacc : log1pf(expf(sacc));
        scs[t] = sacc * tanhf(sp);
    }
    __syncthreads();

    // softmax over relations per (ln, h)
    if (t < 32) {
        int base = (t >> 2) * 16 + (t & 3) * 4;
        float mx = -1e30f;
#pragma unroll
        for (int r = 0; r < 4; r++) mx = fmaxf(mx, scs[base + r]);
        float ev[4], ssum = 0.f;
#pragma unroll
        for (int r = 0; r < 4; r++) { ev[r] = expf(scs[base + r] - mx); ssum += ev[r]; }
#pragma unroll
        for (int r = 0; r < 4; r++) alps[base + r] = ev[r] / ssum;
    }
    __syncthreads();

    // per node: weighted sum + skip + bias + ELU + LayerNorm
    int hh = t >> 6, f = t & 63;
    int wid = t >> 5, lane = t & 31;
#pragma unroll 1
    for (int s = 0; s < 8; s++) {
        int n = node0 + s;
        int rb = s * 16 + hh * 4;
        float o = 0.f;
#pragma unroll
        for (int r = 0; r < 4; r++) {
            const __nv_bfloat16* ap = Asp + (rb + r) * NS;
            float a = __bfloat162float(ap[f]) + __bfloat162float(ap[64 + f]);
            o = fmaf(a, alps[rb + r], o);
        }
        o += g_ps[(size_t)n * CTOT + CPROJ + t];
        o += bias[t];
        o = (o > 0.f) ? o : expm1f(o);

        float s1 = o, s2 = o * o;
#pragma unroll
        for (int off = 16; off > 0; off >>= 1) {
            s1 += __shfl_down_sync(0xffffffffu, s1, off);
            s2 += __shfl_down_sync(0xffffffffu, s2, off);
        }
        if (lane == 0) { red[wid] = s1; red[8 + wid] = s2; }
        __syncthreads();
        if (t == 0) {
            float S1 = 0.f, S2 = 0.f;
#pragma unroll
            for (int w = 0; w < 8; w++) { S1 += red[w]; S2 += red[8 + w]; }
            float mu = S1 * (1.f / 256.f);
            float var = S2 * (1.f / 256.f) - mu * mu;
            red[16] = mu;
            red[17] = rsqrtf(var + 1e-5f);
        }
        __syncthreads();
        float mu = red[16], rstd = red[17];
        out[(size_t)n * 256 + t] = (o - mu) * rstd * gamma[t] + beta[t];
        __syncthreads();
    }
}

// ---------------- launch ----------------
extern "C" void kernel_launch(void* const* d_in, const int* in_sizes, int n_in,
                              void* d_out, int out_size) {
    const float* x         = (const float*)d_in[0];
    const int*   src       = (const int*)d_in[1];
    const int*   trg       = (const int*)d_in[2];
    const int*   rel       = (const int*)d_in[3];
    // d_in[4] = node_to_graph_map (unused)
    const float* W_proj    = (const float*)d_in[5];
    const float* score_src = (const float*)d_in[6];
    const float* score_trg = (const float*)d_in[7];
    const float* W1        = (const float*)d_in[8];
    const float* b1        = (const float*)d_in[9];
    const float* W2        = (const float*)d_in[10];
    const float* b2        = (const float*)d_in[11];
    const float* W3        = (const float*)d_in[12];
    const float* b3        = (const float*)d_in[13];
    const float* W_skip    = (const float*)d_in[14];
    const float* bias      = (const float*)d_in[15];
    const float* gamma     = (const float*)d_in[16];
    const float* beta      = (const float*)d_in[17];
    float* out = (float*)d_out;

    // opt-in to >48KB dynamic smem (idempotent; not a stream op, graph-safe)
    cudaFuncSetAttribute(node2_kernel, cudaFuncAttributeMaxDynamicSharedMemorySize, NODE2_SMEM);

    prep_wext_kernel<<<(CTOT * FIN + 511) / 512, 512>>>(W_proj, W_skip);
    prep_aext_kernel<<<8192, 256>>>(x);
    zero_kernel<<<8192, 256>>>();

    dim3 ggrid(CTOT / 128, (NN + 127) / 128);
    gemm_bf16_kernel<<<ggrid, 256>>>();

    scores_kernel<<<NN, 256>>>(score_src, score_trg);

    int eb = (NE + 255) / 256;
    edge1_kernel<<<eb, 256>>>(src, trg, rel);
    edge2_kernel<<<eb, 256>>>(trg, rel);
    edge3_kernel<<<(NE * 32 + 255) / 256, 256>>>(src, trg, rel);

    node2_kernel<<<NN / 8, 256, NODE2_SMEM>>>(W1, b1, W2, b2, W3, b3, bias, gamma, beta, out);
}

// round 5
// speedup vs baseline: 1.6734x; 1.1361x over previous
#include <cuda_runtime.h>
#include <cuda_bf16.h>
#include <math.h>

// Problem constants
#define NN     50000
#define FIN    256
#define NH     4
#define NR     4
#define FF     64
#define NE     500000
#define CPROJ  1024          // NH*NR*FF
#define CTOT   1280          // CPROJ + NH*FF (skip)
#define KEXT   768           // 3 * FIN (split-bf16 compensated K)
#define NSEG   (NN * NR)     // 200000 (trg, rel) segments
#define NB1    ((NSEG + 1023) / 1024)   // 196 scan blocks

// ---------------- scratch (device globals; no allocation allowed) ----------------
__device__ float         g_ps[(size_t)NN * CTOT];          // [n][1280]: proj | skip (fp32)
__device__ float         g_agg[(size_t)NN * NR * NH * FF]; // [((n*4+r)*4+h)*64+f]
__device__ float         g_ssrc[(size_t)NN * NH * NR];     // [n*16 + h*4 + r]
__device__ float         g_strg[(size_t)NN * NH * NR];
__device__ unsigned      g_m_u[NR * NH];
__device__ __nv_bfloat16 g_aext[(size_t)NN * KEXT];        // [n][768] = [x_hi | x_lo | x_hi]
__device__ __nv_bfloat16 g_bext[(size_t)CTOT * KEXT];      // [c][768] = [W_hi | W_hi | W_lo]
// edge sort scratch
__device__ int           g_cnt[NSEG];
__device__ int           g_off[NSEG + 1];
__device__ int           g_cur[NSEG];
__device__ int           g_bsum[256];
__device__ int           g_psrc[NE];                       // src[], permuted by segment

// ---------------- helpers ----------------
__device__ __forceinline__ unsigned fenc(float f) {
    unsigned u = __float_as_uint(f);
    return (u & 0x80000000u) ? ~u : (u | 0x80000000u);
}
__device__ __forceinline__ float fdec(unsigned u) {
    return (u & 0x80000000u) ? __uint_as_float(u & 0x7fffffffu) : __uint_as_float(~u);
}
__device__ __forceinline__ void bsplit(float w, __nv_bfloat16& hi, __nv_bfloat16& lo) {
    hi = __float2bfloat16(w);
    lo = __float2bfloat16(w - __bfloat162float(hi));
}
__device__ __forceinline__ void mma_bf16(float* c, unsigned a0, unsigned a1, unsigned a2,
                                         unsigned a3, unsigned b0, unsigned b1) {
    asm volatile(
        "mma.sync.aligned.m16n8k16.row.col.f32.bf16.bf16.f32 "
        "{%0,%1,%2,%3}, {%4,%5,%6,%7}, {%8,%9}, {%0,%1,%2,%3};\n"
        : "+f"(c[0]), "+f"(c[1]), "+f"(c[2]), "+f"(c[3])
        : "r"(a0), "r"(a1), "r"(a2), "r"(a3), "r"(b0), "r"(b1));
}

// ---------------- prep kernels ----------------
__global__ void prep_wext_kernel(const float* __restrict__ Wp, const float* __restrict__ Ws) {
    int idx = blockIdx.x * blockDim.x + threadIdx.x;
    if (idx >= CTOT * FIN) return;
    int c = idx >> 8, k = idx & 255;
    float w = (c < CPROJ) ? Wp[idx] : Ws[(c - CPROJ) * FIN + k];
    __nv_bfloat16 hi, lo; bsplit(w, hi, lo);
    size_t b = (size_t)c * KEXT;
    g_bext[b + k] = hi; g_bext[b + 256 + k] = hi; g_bext[b + 512 + k] = lo;
}

__global__ void prep_aext_kernel(const float* __restrict__ x) {
    int idx = blockIdx.x * blockDim.x + threadIdx.x;
    int tot = NN * FIN;
    for (; idx < tot; idx += gridDim.x * blockDim.x) {
        int n = idx >> 8, k = idx & 255;
        float w = x[idx];
        __nv_bfloat16 hi, lo; bsplit(w, hi, lo);
        size_t b = (size_t)n * KEXT;
        g_aext[b + k] = hi; g_aext[b + 256 + k] = lo; g_aext[b + 512 + k] = hi;
    }
}

// ---------------- K1: zero small scratch (counters + maxes) ----------------
__global__ void zero_kernel() {
    int idx = blockIdx.x * blockDim.x + threadIdx.x;
    for (int i = idx; i < NSEG; i += gridDim.x * blockDim.x) g_cnt[i] = 0;
    if (idx < NR * NH) g_m_u[idx] = 0u;
}

// ---------------- K2: bf16 tensor-core GEMM  C[N,1280] = Aext[N,768] @ Bext^T ----------------
#define GS 40   // smem row stride in halves
__global__ void __launch_bounds__(256) gemm_bf16_kernel() {
    __shared__ __nv_bfloat16 As[128 * GS];
    __shared__ __nv_bfloat16 Bs[128 * GS];
    int t = threadIdx.x;
    int lane = t & 31, w = t >> 5;
    int wm = w >> 2, wn = w & 3;
    int g = lane >> 2, tg = lane & 3;
    int row0 = blockIdx.y * 128;
    int col0 = blockIdx.x * 128;

    float acc[4][4][4];
#pragma unroll
    for (int i = 0; i < 4; i++)
#pragma unroll
        for (int j = 0; j < 4; j++)
#pragma unroll
            for (int q = 0; q < 4; q++) acc[i][j][q] = 0.f;

    int ar0 = t >> 2,          ac0 = (t & 3) * 8;
    int ar1 = (t + 256) >> 2,  ac1 = ((t + 256) & 3) * 8;

    for (int k0 = 0; k0 < KEXT; k0 += 32) {
        float4 av0 = make_float4(0.f, 0.f, 0.f, 0.f), av1 = av0;
        if (row0 + ar0 < NN) av0 = *reinterpret_cast<const float4*>(g_aext + (size_t)(row0 + ar0) * KEXT + k0 + ac0);
        if (row0 + ar1 < NN) av1 = *reinterpret_cast<const float4*>(g_aext + (size_t)(row0 + ar1) * KEXT + k0 + ac1);
        float4 bv0 = *reinterpret_cast<const float4*>(g_bext + (size_t)(col0 + ar0) * KEXT + k0 + ac0);
        float4 bv1 = *reinterpret_cast<const float4*>(g_bext + (size_t)(col0 + ar1) * KEXT + k0 + ac1);
        __syncthreads();
        *reinterpret_cast<float4*>(As + ar0 * GS + ac0) = av0;
        *reinterpret_cast<float4*>(As + ar1 * GS + ac1) = av1;
        *reinterpret_cast<float4*>(Bs + ar0 * GS + ac0) = bv0;
        *reinterpret_cast<float4*>(Bs + ar1 * GS + ac1) = bv1;
        __syncthreads();

#pragma unroll
        for (int kk = 0; kk < 32; kk += 16) {
            unsigned af[4][4], bf_[4][2];
#pragma unroll
            for (int mt = 0; mt < 4; mt++) {
                const __nv_bfloat16* ap = As + (wm * 64 + mt * 16 + g) * GS + kk + tg * 2;
                af[mt][0] = *reinterpret_cast<const unsigned*>(ap);
                af[mt][1] = *reinterpret_cast<const unsigned*>(ap + 8 * GS);
                af[mt][2] = *reinterpret_cast<const unsigned*>(ap + 8);
                af[mt][3] = *reinterpret_cast<const unsigned*>(ap + 8 * GS + 8);
            }
#pragma unroll
            for (int nt = 0; nt < 4; nt++) {
                const __nv_bfloat16* bp = Bs + (wn * 32 + nt * 8 + g) * GS + kk + tg * 2;
                bf_[nt][0] = *reinterpret_cast<const unsigned*>(bp);
                bf_[nt][1] = *reinterpret_cast<const unsigned*>(bp + 8);
            }
#pragma unroll
            for (int mt = 0; mt < 4; mt++)
#pragma unroll
                for (int nt = 0; nt < 4; nt++)
                    mma_bf16(acc[mt][nt], af[mt][0], af[mt][1], af[mt][2], af[mt][3],
                             bf_[nt][0], bf_[nt][1]);
        }
    }

#pragma unroll
    for (int mt = 0; mt < 4; mt++)
#pragma unroll
        for (int nt = 0; nt < 4; nt++) {
            int row = row0 + wm * 64 + mt * 16 + g;
            int col = col0 + wn * 32 + nt * 8 + tg * 2;
            if (row < NN) {
                float2 o = make_float2(acc[mt][nt][0], acc[mt][nt][1]);
                *reinterpret_cast<float2*>(g_ps + (size_t)row * CTOT + col) = o;
            }
            if (row + 8 < NN) {
                float2 o = make_float2(acc[mt][nt][2], acc[mt][nt][3]);
                *reinterpret_cast<float2*>(g_ps + (size_t)(row + 8) * CTOT + col) = o;
            }
        }
}

// ---------------- K3: attention scores per (n,h,r) ----------------
__global__ void __launch_bounds__(256) scores_kernel(const float* __restrict__ score_src,
                                                     const float* __restrict__ score_trg) {
    int n = blockIdx.x;
    int t = threadIdx.x;
    int w = t >> 5, lane = t & 31;
    const float* pr_base = g_ps + (size_t)n * CTOT;
#pragma unroll
    for (int pi = 0; pi < 2; pi++) {
        int p = w * 2 + pi;   // p = h*4 + r
        const float* pr = pr_base + p * 64;
        float v1 = pr[lane] * score_src[p * 64 + lane] + pr[lane + 32] * score_src[p * 64 + lane + 32];
        float v2 = pr[lane] * score_trg[p * 64 + lane] + pr[lane + 32] * score_trg[p * 64 + lane + 32];
#pragma unroll
        for (int off = 16; off > 0; off >>= 1) {
            v1 += __shfl_down_sync(0xffffffffu, v1, off);
            v2 += __shfl_down_sync(0xffffffffu, v2, off);
        }
        if (lane == 0) {
            g_ssrc[n * 16 + p] = v1;
            g_strg[n * 16 + p] = v2;
        }
    }
}

// ---------------- K4: edge pass 1 — per-(rel,head) max only ----------------
__global__ void __launch_bounds__(256) edge1_kernel(const int* __restrict__ src,
                                                    const int* __restrict__ trg,
                                                    const int* __restrict__ rel) {
    __shared__ unsigned sm[16];
    int t = threadIdx.x;
    if (t < 16) sm[t] = 0u;
    __syncthreads();
    int e = blockIdx.x * 256 + t;
    if (e < NE) {
        int r = rel[e];
        int is = src[e] * 16;
        int it = trg[e] * 16;
#pragma unroll
        for (int h = 0; h < NH; h++) {
            float v = g_ssrc[is + h * 4 + r] + g_strg[it + h * 4 + r];
            v = (v > 0.f) ? v : 0.2f * v;
            atomicMax(&sm[r * 4 + h], fenc(v));
        }
    }
    __syncthreads();
    if (t < 16 && sm[t] != 0u) atomicMax(&g_m_u[t], sm[t]);
}

// ---------------- counting sort: hist / scan x3 / scatter ----------------
__global__ void hist_kernel(const int* __restrict__ trg, const int* __restrict__ rel) {
    int e = blockIdx.x * 256 + threadIdx.x;
    if (e < NE) atomicAdd(&g_cnt[trg[e] * 4 + rel[e]], 1);
}

__global__ void __launch_bounds__(1024) scan1_kernel() {
    __shared__ int sd[1024];
    int t = threadIdx.x;
    int i = blockIdx.x * 1024 + t;
    int v = (i < NSEG) ? g_cnt[i] : 0;
    sd[t] = v;
    __syncthreads();
#pragma unroll
    for (int off = 1; off < 1024; off <<= 1) {
        int u = (t >= off) ? sd[t - off] : 0;
        __syncthreads();
        sd[t] += u;
        __syncthreads();
    }
    if (i < NSEG) g_off[i] = sd[t] - v;   // exclusive within block
    if (t == 1023) g_bsum[blockIdx.x] = sd[t];
}

__global__ void __launch_bounds__(256) scan2_kernel() {
    __shared__ int sd[256];
    int t = threadIdx.x;
    int v = (t < NB1) ? g_bsum[t] : 0;
    sd[t] = v;
    __syncthreads();
#pragma unroll
    for (int off = 1; off < 256; off <<= 1) {
        int u = (t >= off) ? sd[t - off] : 0;
        __syncthreads();
        sd[t] += u;
        __syncthreads();
    }
    if (t < NB1) g_bsum[t] = sd[t] - v;   // exclusive block bases
    if (t == 0) g_off[NSEG] = NE;
}

__global__ void __launch_bounds__(1024) scan3_kernel() {
    int i = blockIdx.x * 1024 + threadIdx.x;
    if (i < NSEG) {
        int o = g_off[i] + g_bsum[blockIdx.x];
        g_off[i] = o;
        g_cur[i] = o;
    }
}

__global__ void scatter_kernel(const int* __restrict__ src, const int* __restrict__ trg,
                               const int* __restrict__ rel) {
    int e = blockIdx.x * 256 + threadIdx.x;
    if (e >= NE) return;
    int seg = trg[e] * 4 + rel[e];
    int pos = atomicAdd(&g_cur[seg], 1);
    g_psrc[pos] = src[e];
}

// ---------------- K6: atomic-free segment aggregation (one warp per segment) ----------------
__global__ void __launch_bounds__(256) edge_agg_kernel() {
    int gw = (blockIdx.x * blockDim.x + threadIdx.x) >> 5;
    int lane = threadIdx.x & 31;
    if (gw >= NSEG) return;
    int seg = gw;
    int tg = seg >> 2, r = seg & 3;
    int beg = g_off[seg], end = g_off[seg + 1];

    float strg_h[4], m_h[4];
#pragma unroll
    for (int h = 0; h < 4; h++) {
        strg_h[h] = g_strg[tg * 16 + h * 4 + r];
        m_h[h]    = fdec(g_m_u[r * 4 + h]);
    }
    float num0[4] = {0.f, 0.f, 0.f, 0.f};
    float num1[4] = {0.f, 0.f, 0.f, 0.f};
    float den[4]  = {0.f, 0.f, 0.f, 0.f};

    for (int i = beg; i < end; i++) {
        int s = g_psrc[i];
        const float* pb = g_ps + (size_t)s * CTOT + r * 64;
        const float* sp = g_ssrc + s * 16 + r;
#pragma unroll
        for (int h = 0; h < 4; h++) {
            float v = sp[h * 4] + strg_h[h];
            v = (v > 0.f) ? v : 0.2f * v;
            float ex = expf(v - m_h[h]);
            den[h] += ex;
            const float* pp = pb + h * 256;
            num0[h] = fmaf(ex, pp[lane],      num0[h]);
            num1[h] = fmaf(ex, pp[lane + 32], num1[h]);
        }
    }
#pragma unroll
    for (int h = 0; h < 4; h++) {
        float inv = 1.f / (den[h] + 1e-16f);
        float* ag = g_agg + ((size_t)seg * 4 + h) * 64;
        ag[lane]      = num0[h] * inv;
        ag[lane + 32] = num1[h] * inv;
    }
}

// ---------------- K7: fused node kernel with tensor-core MLP ----------------
#define NS 200
#define NODE2_SMEM (128*NS*2*2 + 64*NS*2*2 + (64+64+64+128+128+32)*4)

__device__ __forceinline__ void mlp_layer(const __nv_bfloat16* __restrict__ Ain,
                                          const __nv_bfloat16* __restrict__ Wm,
                                          const float* __restrict__ bs,
                                          __nv_bfloat16* __restrict__ Hout, int t) {
    int lane = t & 31, w = t >> 5;
    int wm = w >> 2, wn = w & 3;
    int g = lane >> 2, tg = lane & 3;
    float acc[4][2][4];
#pragma unroll
    for (int i = 0; i < 4; i++)
#pragma unroll
        for (int j = 0; j < 2; j++)
#pragma unroll
            for (int q = 0; q < 4; q++) acc[i][j][q] = 0.f;

#pragma unroll
    for (int ks = 0; ks < 12; ks++) {
        int kk = ks * 16;
        unsigned af[4][4], bf_[2][2];
#pragma unroll
        for (int mt = 0; mt < 4; mt++) {
            const __nv_bfloat16* ap = Ain + (wm * 64 + mt * 16 + g) * NS + kk + tg * 2;
            af[mt][0] = *reinterpret_cast<const unsigned*>(ap);
            af[mt][1] = *reinterpret_cast<const unsigned*>(ap + 8 * NS);
            af[mt][2] = *reinterpret_cast<const unsigned*>(ap + 8);
            af[mt][3] = *reinterpret_cast<const unsigned*>(ap + 8 * NS + 8);
        }
#pragma unroll
        for (int nt = 0; nt < 2; nt++) {
            const __nv_bfloat16* bp = Wm + (wn * 16 + nt * 8 + g) * NS + kk + tg * 2;
            bf_[nt][0] = *reinterpret_cast<const unsigned*>(bp);
            bf_[nt][1] = *reinterpret_cast<const unsigned*>(bp + 8);
        }
#pragma unroll
        for (int mt = 0; mt < 4; mt++)
#pragma unroll
            for (int nt = 0; nt < 2; nt++)
                mma_bf16(acc[mt][nt], af[mt][0], af[mt][1], af[mt][2], af[mt][3],
                         bf_[nt][0], bf_[nt][1]);
    }
    __syncthreads();
#pragma unroll
    for (int mt = 0; mt < 4; mt++)
#pragma unroll
        for (int nt = 0; nt < 2; nt++) {
            int row = wm * 64 + mt * 16 + g;
            int col = wn * 16 + nt * 8 + tg * 2;
#pragma unroll
            for (int q = 0; q < 4; q++) {
                int rr = row + ((q >> 1) ? 8 : 0);
                int cc = col + (q & 1);
                float h = fmaxf(acc[mt][nt][q] + bs[cc], 0.f);
                __nv_bfloat16 hi, lo; bsplit(h, hi, lo);
                Hout[rr * NS + cc] = hi;
                Hout[rr * NS + 64 + cc] = lo;
                Hout[rr * NS + 128 + cc] = hi;
            }
        }
    __syncthreads();
}

__global__ void __launch_bounds__(256) node2_kernel(
        const float* __restrict__ W1, const float* __restrict__ b1,
        const float* __restrict__ W2, const float* __restrict__ b2,
        const float* __restrict__ W3, const float* __restrict__ b3,
        const float* __restrict__ bias, const float* __restrict__ gamma,
        const float* __restrict__ beta, float* __restrict__ out) {
    extern __shared__ char nsm[];
    __nv_bfloat16* Asp = reinterpret_cast<__nv_bfloat16*>(nsm);
    __nv_bfloat16* Hsp = Asp + 128 * NS;
    __nv_bfloat16* W1s = Hsp + 128 * NS;
    __nv_bfloat16* W2s = W1s + 64 * NS;
    float* W3s  = reinterpret_cast<float*>(W2s + 64 * NS);
    float* b1s  = W3s + 64;
    float* b2s  = b1s + 64;
    float* scs  = b2s + 64;
    float* alps = scs + 128;
    float* red  = alps + 128;

    int t = threadIdx.x;
    int node0 = blockIdx.x * 8;

    for (int idx = t; idx < 4096; idx += 256) {
        int n_ = idx >> 6, k_ = idx & 63;
        __nv_bfloat16 hi, lo;
        bsplit(W1[idx], hi, lo);
        W1s[n_ * NS + k_] = hi; W1s[n_ * NS + 64 + k_] = hi; W1s[n_ * NS + 128 + k_] = lo;
        bsplit(W2[idx], hi, lo);
        W2s[n_ * NS + k_] = hi; W2s[n_ * NS + 64 + k_] = hi; W2s[n_ * NS + 128 + k_] = lo;
    }
    if (t < 64) { W3s[t] = W3[t]; b1s[t] = b1[t]; b2s[t] = b2[t]; }

    for (int idx = t; idx < 8192; idx += 256) {
        int row = idx >> 6, f = idx & 63;
        int ln = row >> 4, p = row & 15, h = p >> 2, r = p & 3;
        int n = node0 + ln;
        float a = g_agg[(((size_t)n * 4 + r) * 4 + h) * 64 + f];
        __nv_bfloat16 hi, lo; bsplit(a, hi, lo);
        Asp[row * NS + f] = hi; Asp[row * NS + 64 + f] = lo; Asp[row * NS + 128 + f] = hi;
    }
    __syncthreads();

    mlp_layer(Asp, W1s, b1s, Hsp, t);
    mlp_layer(Hsp, W2s, b2s, Hsp, t);

    if (t < 128) {
        float sacc = b3[0];
        const __nv_bfloat16* hp = Hsp + t * NS;
#pragma unroll
        for (int j = 0; j < 64; j++) {
            float hv = __bfloat162float(hp[j]) + __bfloat162float(hp[64 + j]);
            sacc = fmaf(hv, W3s[j], sacc);
        }
        float sp = (sacc > 20.f) ? sacc : log1pf(expf(sacc));
        scs[t] = sacc * tanhf(sp);
    }
    __syncthreads();

    if (t < 32) {
        int base = (t >> 2) * 16 + (t & 3) * 4;
        float mx = -1e30f;
#pragma unroll
        for (int r = 0; r < 4; r++) mx = fmaxf(mx, scs[base + r]);
        float ev[4], ssum = 0.f;
#pragma unroll
        for (int r = 0; r < 4; r++) { ev[r] = expf(scs[base + r] - mx); ssum += ev[r]; }
#pragma unroll
        for (int r = 0; r < 4; r++) alps[base + r] = ev[r] / ssum;
    }
    __syncthreads();

    int hh = t >> 6, f = t & 63;
    int wid = t >> 5, lane = t & 31;
#pragma unroll 1
    for (int s = 0; s < 8; s++) {
        int n = node0 + s;
        int rb = s * 16 + hh * 4;
        float o = 0.f;
#pragma unroll
        for (int r = 0; r < 4; r++) {
            const __nv_bfloat16* ap = Asp + (rb + r) * NS;
            float a = __bfloat162float(ap[f]) + __bfloat162float(ap[64 + f]);
            o = fmaf(a, alps[rb + r], o);
        }
        o += g_ps[(size_t)n * CTOT + CPROJ + t];
        o += bias[t];
        o = (o > 0.f) ? o : expm1f(o);

        float s1 = o, s2 = o * o;
#pragma unroll
        for (int off = 16; off > 0; off >>= 1) {
            s1 += __shfl_down_sync(0xffffffffu, s1, off);
            s2 += __shfl_down_sync(0xffffffffu, s2, off);
        }
        if (lane == 0) { red[wid] = s1; red[8 + wid] = s2; }
        __syncthreads();
        if (t == 0) {
            float S1 = 0.f, S2 = 0.f;
#pragma unroll
            for (int w = 0; w < 8; w++) { S1 += red[w]; S2 += red[8 + w]; }
            float mu = S1 * (1.f / 256.f);
            float var = S2 * (1.f / 256.f) - mu * mu;
            red[16] = mu;
            red[17] = rsqrtf(var + 1e-5f);
        }
        __syncthreads();
        float mu = red[16], rstd = red[17];
        out[(size_t)n * 256 + t] = (o - mu) * rstd * gamma[t] + beta[t];
        __syncthreads();
    }
}

// ---------------- launch ----------------
extern "C" void kernel_launch(void* const* d_in, const int* in_sizes, int n_in,
                              void* d_out, int out_size) {
    const float* x         = (const float*)d_in[0];
    const int*   src       = (const int*)d_in[1];
    const int*   trg       = (const int*)d_in[2];
    const int*   rel       = (const int*)d_in[3];
    // d_in[4] = node_to_graph_map (unused)
    const float* W_proj    = (const float*)d_in[5];
    const float* score_src = (const float*)d_in[6];
    const float* score_trg = (const float*)d_in[7];
    const float* W1        = (const float*)d_in[8];
    const float* b1        = (const float*)d_in[9];
    const float* W2        = (const float*)d_in[10];
    const float* b2        = (const float*)d_in[11];
    const float* W3        = (const float*)d_in[12];
    const float* b3        = (const float*)d_in[13];
    const float* W_skip    = (const float*)d_in[14];
    const float* bias      = (const float*)d_in[15];
    const float* gamma     = (const float*)d_in[16];
    const float* beta      = (const float*)d_in[17];
    float* out = (float*)d_out;

    cudaFuncSetAttribute(node2_kernel, cudaFuncAttributeMaxDynamicSharedMemorySize, NODE2_SMEM);

    prep_wext_kernel<<<(CTOT * FIN + 511) / 512, 512>>>(W_proj, W_skip);
    prep_aext_kernel<<<8192, 256>>>(x);
    zero_kernel<<<784, 256>>>();

    dim3 ggrid(CTOT / 128, (NN + 127) / 128);
    gemm_bf16_kernel<<<ggrid, 256>>>();

    scores_kernel<<<NN, 256>>>(score_src, score_trg);

    int eb = (NE + 255) / 256;
    edge1_kernel<<<eb, 256>>>(src, trg, rel);

    // counting sort by (trg, rel)
    hist_kernel<<<eb, 256>>>(trg, rel);
    scan1_kernel<<<NB1, 1024>>>();
    scan2_kernel<<<1, 256>>>();
    scan3_kernel<<<NB1, 1024>>>();
    scatter_kernel<<<eb, 256>>>(src, trg, rel);

    // atomic-free aggregation
    edge_agg_kernel<<<(NSEG * 32 + 255) / 256, 256>>>();

    node2_kernel<<<NN / 8, 256, NODE2_SMEM>>>(W1, b1, W2, b2, W3, b3, bias, gamma, beta, out);
}